// round 9
// baseline (speedup 1.0000x reference)
#include <cuda_runtime.h>
#include <cstdint>

typedef unsigned long long ull;

#define TPB   256
#define R_    16
#define D_    1024
#define NWARP 8            // warps per block = column chunks per row
#define MAXROWS 65536

// ---- packed f32x2 helpers ----
__device__ __forceinline__ ull ffma2(ull a, ull b, ull c) {
    ull d;
    asm("fma.rn.f32x2 %0, %1, %2, %3;" : "=l"(d) : "l"(a), "l"(b), "l"(c));
    return d;
}
__device__ __forceinline__ ull fmul2(ull a, ull b) {
    ull d;
    asm("mul.rn.f32x2 %0, %1, %2;" : "=l"(d) : "l"(a), "l"(b));
    return d;
}
__device__ __forceinline__ float lo_(ull v) { return __int_as_float((int)(unsigned)(v & 0xffffffffull)); }
__device__ __forceinline__ float hi_(ull v) { return __int_as_float((int)(unsigned)(v >> 32)); }
__device__ __forceinline__ ull   dup_(float v) {
    ull d;
    asm("mov.b64 %0, {%1, %1};" : "=l"(d) : "r"(__float_as_uint(v)));
    return d;
}
__device__ __forceinline__ ulonglong2 ldg128(const void* p) {
    ulonglong2 v;
    asm("ld.global.nc.v2.u64 {%0, %1}, [%2];" : "=l"(v.x), "=l"(v.y) : "l"(p));
    return v;
}
__device__ __forceinline__ void stcs128(void* p, ull a, ull b) {
    asm volatile("st.global.cs.v2.u64 [%0], {%1, %2};" :: "l"(p), "l"(a), "l"(b));
}

// scratch (static device memory — allowed)
__device__ float4 g_part[MAXROWS * NWARP];   // per (row, warp-chunk): x2, y2, xy
__device__ float2 g_coef[MAXROWS];           // per row: cx, cy

// ---- helper: rank-16 delta for this thread's 4 columns ----
__device__ __forceinline__ void delta4(const float4 b[4], const ulonglong2 a2[R_],
                                       ull& d01, ull& d23)
{
    ull e01, e23;
    {
        ull bb = dup_(b[0].x);
        d01 = fmul2(bb, a2[0].x); d23 = fmul2(bb, a2[0].y);
        bb = dup_(b[0].y);
        e01 = fmul2(bb, a2[1].x); e23 = fmul2(bb, a2[1].y);
        bb = dup_(b[0].z);
        d01 = ffma2(bb, a2[2].x, d01); d23 = ffma2(bb, a2[2].y, d23);
        bb = dup_(b[0].w);
        e01 = ffma2(bb, a2[3].x, e01); e23 = ffma2(bb, a2[3].y, e23);
    }
    #pragma unroll
    for (int q = 1; q < 4; ++q) {
        ull bb = dup_(b[q].x);
        d01 = ffma2(bb, a2[4 * q + 0].x, d01); d23 = ffma2(bb, a2[4 * q + 0].y, d23);
        bb = dup_(b[q].y);
        e01 = ffma2(bb, a2[4 * q + 1].x, e01); e23 = ffma2(bb, a2[4 * q + 1].y, e23);
        bb = dup_(b[q].z);
        d01 = ffma2(bb, a2[4 * q + 2].x, d01); d23 = ffma2(bb, a2[4 * q + 2].y, d23);
        bb = dup_(b[q].w);
        e01 = ffma2(bb, a2[4 * q + 3].x, e01); e23 = ffma2(bb, a2[4 * q + 3].y, e23);
    }
    ull s01, s23;
    asm("add.rn.f32x2 %0, %1, %2;" : "=l"(s01) : "l"(d01), "l"(e01));
    asm("add.rn.f32x2 %0, %1, %2;" : "=l"(s23) : "l"(d23), "l"(e23));
    d01 = s01; d23 = s23;
}

__device__ __forceinline__ void loadB(const float* __restrict__ loraB, int idx, float4 b[4])
{
    if (idx >= 0) {
        const float4* p = reinterpret_cast<const float4*>(loraB + (size_t)idx * R_);
        b[0] = __ldg(p); b[1] = __ldg(p + 1); b[2] = __ldg(p + 2); b[3] = __ldg(p + 3);
    } else {
        b[0] = b[1] = b[2] = b[3] = make_float4(0.f, 0.f, 0.f, 0.f);
    }
}

// ================= Kernel A: partial sums (barrier-free) =================
__global__ __launch_bounds__(TPB, 2)
void kA(const int*   __restrict__ indices,
        const float* __restrict__ baseW,
        const float* __restrict__ loraA,
        const float* __restrict__ loraB,
        int n_rows)
{
    const int tid  = threadIdx.x;
    const int wid  = tid >> 5;
    const int lane = tid & 31;
    const int d0   = tid * 4;

    ulonglong2 a2[R_];
    #pragma unroll
    for (int r = 0; r < R_; ++r) a2[r] = ldg128(loraA + r * D_ + d0);

    const int G = gridDim.x;
    int g = blockIdx.x;

    int idx_c = (g < n_rows) ? __ldg(indices + g) : -1;
    int idx_n = (g + G < n_rows) ? __ldg(indices + g + G) : -1;
    ulonglong2 x_c = (idx_c >= 0) ? ldg128(baseW + (size_t)idx_c * D_ + d0)
                                  : make_ulonglong2(0ull, 0ull);

    for (; g < n_rows; g += G) {
        // pipeline: idx depth-2, x depth-1
        int idx_nn = (g + 2 * G < n_rows) ? __ldg(indices + g + 2 * G) : -1;
        ulonglong2 x_n = (idx_n >= 0) ? ldg128(baseW + (size_t)idx_n * D_ + d0)
                                      : make_ulonglong2(0ull, 0ull);
        float4 b[4];
        loadB(loraB, idx_c, b);

        ull d01, d23;
        delta4(b, a2, d01, d23);

        float x0 = lo_(x_c.x), x1 = hi_(x_c.x), x2c = lo_(x_c.y), x3 = hi_(x_c.y);
        float y0 = lo_(d01),   y1 = hi_(d01),   y2c = lo_(d23),   y3 = hi_(d23);

        // raw delta is 0.1 * (b @ A) — fold SCALING into partials via y*0.1 later?
        // No: keep delta unscaled here; scaling folded in kernel B/C consistently.
        float sx2 = fmaf(x0, x0, fmaf(x1, x1, fmaf(x2c, x2c, x3 * x3)));
        float sy2 = fmaf(y0, y0, fmaf(y1, y1, fmaf(y2c, y2c, y3 * y3)));
        float sxy = fmaf(x0, y0, fmaf(x1, y1, fmaf(x2c, y2c, x3 * y3)));

        #pragma unroll
        for (int off = 16; off > 0; off >>= 1) {
            sx2 += __shfl_xor_sync(0xffffffffu, sx2, off);
            sy2 += __shfl_xor_sync(0xffffffffu, sy2, off);
            sxy += __shfl_xor_sync(0xffffffffu, sxy, off);
        }
        if (lane == 0)
            g_part[(g << 3) | wid] = make_float4(sx2, sy2, sxy, 0.f);

        idx_c = idx_n; idx_n = idx_nn; x_c = x_n;
    }
}

// ================= Kernel B: reduce chunks + epilogue =================
__global__ __launch_bounds__(256)
void kB(int n_rows)
{
    int i = blockIdx.x * blockDim.x + threadIdx.x;
    if (i >= n_rows) return;

    float x2 = 0.f, y2r = 0.f, xyr = 0.f;
    #pragma unroll
    for (int w = 0; w < NWARP; ++w) {
        float4 p = g_part[(i << 3) | w];
        x2 += p.x; y2r += p.y; xyr += p.z;
    }
    // delta = SCALING * (b@A): partials were computed on raw b@A
    const float SC = 0.1f;
    float y2 = y2r * (SC * SC);
    float xy = xyr * SC;

    const float MAXN = 1.0f - 1e-5f;
    const float EPSN = 1e-5f;

    float nx = sqrtf(x2);
    float sx = (nx > MAXN) ? __fdividef(MAXN, fmaxf(nx, EPSN)) : 1.0f;
    float ny = sqrtf(y2);
    float sy = (ny > MAXN) ? __fdividef(MAXN, fmaxf(ny, EPSN)) : 1.0f;

    float X2 = sx * sx * x2;
    float Y2 = sy * sy * y2;
    float XY = sx * sy * xy;

    float A_  = 1.0f + 2.0f * XY + Y2;
    float B_  = 1.0f - X2;
    float den = fmaxf(1.0f + 2.0f * XY + X2 * Y2, 1e-15f);

    float n2 = (A_ * A_ * X2 + 2.0f * A_ * B_ * XY + B_ * B_ * Y2) / (den * den);
    float no = sqrtf(fmaxf(n2, 0.0f));
    float sf = (no > MAXN) ? __fdividef(MAXN, fmaxf(no, EPSN)) : 1.0f;

    float cx = __fdividef(sf * A_ * sx, den);
    float cy = __fdividef(sf * B_ * sy, den) * SC;   // fold SCALING into cy
    g_coef[i] = make_float2(cx, cy);
}

// ================= Kernel C: apply (barrier-free) =================
__global__ __launch_bounds__(TPB, 2)
void kC(const int*   __restrict__ indices,
        const float* __restrict__ baseW,
        const float* __restrict__ loraA,
        const float* __restrict__ loraB,
        float*       __restrict__ out,
        int n_rows)
{
    const int tid = threadIdx.x;
    const int d0  = tid * 4;

    ulonglong2 a2[R_];
    #pragma unroll
    for (int r = 0; r < R_; ++r) a2[r] = ldg128(loraA + r * D_ + d0);

    const int G = gridDim.x;
    int g = blockIdx.x;

    int idx_c = (g < n_rows) ? __ldg(indices + g) : -1;
    int idx_n = (g + G < n_rows) ? __ldg(indices + g + G) : -1;
    ulonglong2 x_c = (idx_c >= 0) ? ldg128(baseW + (size_t)idx_c * D_ + d0)
                                  : make_ulonglong2(0ull, 0ull);

    for (; g < n_rows; g += G) {
        int idx_nn = (g + 2 * G < n_rows) ? __ldg(indices + g + 2 * G) : -1;
        ulonglong2 x_n = (idx_n >= 0) ? ldg128(baseW + (size_t)idx_n * D_ + d0)
                                      : make_ulonglong2(0ull, 0ull);
        float2 cf = __ldg(&g_coef[g]);
        float4 b[4];
        loadB(loraB, idx_c, b);

        ull d01, d23;
        delta4(b, a2, d01, d23);

        ull cxd = dup_(cf.x), cyd = dup_(cf.y);
        ull o01 = ffma2(cxd, x_c.x, fmul2(cyd, d01));
        ull o23 = ffma2(cxd, x_c.y, fmul2(cyd, d23));
        stcs128(out + (size_t)g * D_ + d0, o01, o23);

        idx_c = idx_n; idx_n = idx_nn; x_c = x_n;
    }
}

extern "C" void kernel_launch(void* const* d_in, const int* in_sizes, int n_in,
                              void* d_out, int out_size)
{
    const int*   indices = (const int*)  d_in[0];
    const float* baseW   = (const float*)d_in[1];
    const float* loraA   = (const float*)d_in[2];
    const float* loraB   = (const float*)d_in[3];
    float*       out     = (float*)d_out;

    int n_rows = in_sizes[0];                 // 32768
    int gridAC = 2 * 148;                     // 2 CTAs/SM, persistent grid-stride
    if (gridAC > n_rows) gridAC = n_rows;
    int gridB  = (n_rows + 255) / 256;

    kA<<<gridAC, TPB>>>(indices, baseW, loraA, loraB, n_rows);
    kB<<<gridB, 256>>>(n_rows);
    kC<<<gridAC, TPB>>>(indices, baseW, loraA, loraB, out, n_rows);
}

// round 10
// speedup vs baseline: 1.0001x; 1.0001x over previous
#include <cuda_runtime.h>
#include <cstdint>

typedef unsigned long long ull;

#define TPB   256
#define R_    16
#define D_    1024
#define NWARP 8            // warps per block = column chunks per row
#define MAXROWS 65536

// ---- packed f32x2 helpers ----
__device__ __forceinline__ ull ffma2(ull a, ull b, ull c) {
    ull d;
    asm("fma.rn.f32x2 %0, %1, %2, %3;" : "=l"(d) : "l"(a), "l"(b), "l"(c));
    return d;
}
__device__ __forceinline__ ull fmul2(ull a, ull b) {
    ull d;
    asm("mul.rn.f32x2 %0, %1, %2;" : "=l"(d) : "l"(a), "l"(b));
    return d;
}
__device__ __forceinline__ float lo_(ull v) { return __int_as_float((int)(unsigned)(v & 0xffffffffull)); }
__device__ __forceinline__ float hi_(ull v) { return __int_as_float((int)(unsigned)(v >> 32)); }
__device__ __forceinline__ ull   dup_(float v) {
    ull d;
    asm("mov.b64 %0, {%1, %1};" : "=l"(d) : "r"(__float_as_uint(v)));
    return d;
}
__device__ __forceinline__ ulonglong2 ldg128(const void* p) {
    ulonglong2 v;
    asm("ld.global.nc.v2.u64 {%0, %1}, [%2];" : "=l"(v.x), "=l"(v.y) : "l"(p));
    return v;
}
__device__ __forceinline__ void stcs128(void* p, ull a, ull b) {
    asm volatile("st.global.cs.v2.u64 [%0], {%1, %2};" :: "l"(p), "l"(a), "l"(b));
}

// scratch (static device memory — allowed)
__device__ float4 g_part[MAXROWS * NWARP];   // per (row, warp-chunk): x2, y2, xy
__device__ float2 g_coef[MAXROWS];           // per row: cx, cy

// ---- helper: rank-16 delta for this thread's 4 columns ----
__device__ __forceinline__ void delta4(const float4 b[4], const ulonglong2 a2[R_],
                                       ull& d01, ull& d23)
{
    ull e01, e23;
    {
        ull bb = dup_(b[0].x);
        d01 = fmul2(bb, a2[0].x); d23 = fmul2(bb, a2[0].y);
        bb = dup_(b[0].y);
        e01 = fmul2(bb, a2[1].x); e23 = fmul2(bb, a2[1].y);
        bb = dup_(b[0].z);
        d01 = ffma2(bb, a2[2].x, d01); d23 = ffma2(bb, a2[2].y, d23);
        bb = dup_(b[0].w);
        e01 = ffma2(bb, a2[3].x, e01); e23 = ffma2(bb, a2[3].y, e23);
    }
    #pragma unroll
    for (int q = 1; q < 4; ++q) {
        ull bb = dup_(b[q].x);
        d01 = ffma2(bb, a2[4 * q + 0].x, d01); d23 = ffma2(bb, a2[4 * q + 0].y, d23);
        bb = dup_(b[q].y);
        e01 = ffma2(bb, a2[4 * q + 1].x, e01); e23 = ffma2(bb, a2[4 * q + 1].y, e23);
        bb = dup_(b[q].z);
        d01 = ffma2(bb, a2[4 * q + 2].x, d01); d23 = ffma2(bb, a2[4 * q + 2].y, d23);
        bb = dup_(b[q].w);
        e01 = ffma2(bb, a2[4 * q + 3].x, e01); e23 = ffma2(bb, a2[4 * q + 3].y, e23);
    }
    ull s01, s23;
    asm("add.rn.f32x2 %0, %1, %2;" : "=l"(s01) : "l"(d01), "l"(e01));
    asm("add.rn.f32x2 %0, %1, %2;" : "=l"(s23) : "l"(d23), "l"(e23));
    d01 = s01; d23 = s23;
}

__device__ __forceinline__ void loadB(const float* __restrict__ loraB, int idx, float4 b[4])
{
    if (idx >= 0) {
        const float4* p = reinterpret_cast<const float4*>(loraB + (size_t)idx * R_);
        b[0] = __ldg(p); b[1] = __ldg(p + 1); b[2] = __ldg(p + 2); b[3] = __ldg(p + 3);
    } else {
        b[0] = b[1] = b[2] = b[3] = make_float4(0.f, 0.f, 0.f, 0.f);
    }
}

// ================= Kernel A: partial sums (barrier-free) =================
__global__ __launch_bounds__(TPB, 2)
void kA(const int*   __restrict__ indices,
        const float* __restrict__ baseW,
        const float* __restrict__ loraA,
        const float* __restrict__ loraB,
        int n_rows)
{
    const int tid  = threadIdx.x;
    const int wid  = tid >> 5;
    const int lane = tid & 31;
    const int d0   = tid * 4;

    ulonglong2 a2[R_];
    #pragma unroll
    for (int r = 0; r < R_; ++r) a2[r] = ldg128(loraA + r * D_ + d0);

    const int G = gridDim.x;
    int g = blockIdx.x;

    int idx_c = (g < n_rows) ? __ldg(indices + g) : -1;
    int idx_n = (g + G < n_rows) ? __ldg(indices + g + G) : -1;
    ulonglong2 x_c = (idx_c >= 0) ? ldg128(baseW + (size_t)idx_c * D_ + d0)
                                  : make_ulonglong2(0ull, 0ull);

    for (; g < n_rows; g += G) {
        // pipeline: idx depth-2, x depth-1
        int idx_nn = (g + 2 * G < n_rows) ? __ldg(indices + g + 2 * G) : -1;
        ulonglong2 x_n = (idx_n >= 0) ? ldg128(baseW + (size_t)idx_n * D_ + d0)
                                      : make_ulonglong2(0ull, 0ull);
        float4 b[4];
        loadB(loraB, idx_c, b);

        ull d01, d23;
        delta4(b, a2, d01, d23);

        float x0 = lo_(x_c.x), x1 = hi_(x_c.x), x2c = lo_(x_c.y), x3 = hi_(x_c.y);
        float y0 = lo_(d01),   y1 = hi_(d01),   y2c = lo_(d23),   y3 = hi_(d23);

        // raw delta is 0.1 * (b @ A) — fold SCALING into partials via y*0.1 later?
        // No: keep delta unscaled here; scaling folded in kernel B/C consistently.
        float sx2 = fmaf(x0, x0, fmaf(x1, x1, fmaf(x2c, x2c, x3 * x3)));
        float sy2 = fmaf(y0, y0, fmaf(y1, y1, fmaf(y2c, y2c, y3 * y3)));
        float sxy = fmaf(x0, y0, fmaf(x1, y1, fmaf(x2c, y2c, x3 * y3)));

        #pragma unroll
        for (int off = 16; off > 0; off >>= 1) {
            sx2 += __shfl_xor_sync(0xffffffffu, sx2, off);
            sy2 += __shfl_xor_sync(0xffffffffu, sy2, off);
            sxy += __shfl_xor_sync(0xffffffffu, sxy, off);
        }
        if (lane == 0)
            g_part[(g << 3) | wid] = make_float4(sx2, sy2, sxy, 0.f);

        idx_c = idx_n; idx_n = idx_nn; x_c = x_n;
    }
}

// ================= Kernel B: reduce chunks + epilogue =================
__global__ __launch_bounds__(256)
void kB(int n_rows)
{
    int i = blockIdx.x * blockDim.x + threadIdx.x;
    if (i >= n_rows) return;

    float x2 = 0.f, y2r = 0.f, xyr = 0.f;
    #pragma unroll
    for (int w = 0; w < NWARP; ++w) {
        float4 p = g_part[(i << 3) | w];
        x2 += p.x; y2r += p.y; xyr += p.z;
    }
    // delta = SCALING * (b@A): partials were computed on raw b@A
    const float SC = 0.1f;
    float y2 = y2r * (SC * SC);
    float xy = xyr * SC;

    const float MAXN = 1.0f - 1e-5f;
    const float EPSN = 1e-5f;

    float nx = sqrtf(x2);
    float sx = (nx > MAXN) ? __fdividef(MAXN, fmaxf(nx, EPSN)) : 1.0f;
    float ny = sqrtf(y2);
    float sy = (ny > MAXN) ? __fdividef(MAXN, fmaxf(ny, EPSN)) : 1.0f;

    float X2 = sx * sx * x2;
    float Y2 = sy * sy * y2;
    float XY = sx * sy * xy;

    float A_  = 1.0f + 2.0f * XY + Y2;
    float B_  = 1.0f - X2;
    float den = fmaxf(1.0f + 2.0f * XY + X2 * Y2, 1e-15f);

    float n2 = (A_ * A_ * X2 + 2.0f * A_ * B_ * XY + B_ * B_ * Y2) / (den * den);
    float no = sqrtf(fmaxf(n2, 0.0f));
    float sf = (no > MAXN) ? __fdividef(MAXN, fmaxf(no, EPSN)) : 1.0f;

    float cx = __fdividef(sf * A_ * sx, den);
    float cy = __fdividef(sf * B_ * sy, den) * SC;   // fold SCALING into cy
    g_coef[i] = make_float2(cx, cy);
}

// ================= Kernel C: apply (barrier-free) =================
__global__ __launch_bounds__(TPB, 2)
void kC(const int*   __restrict__ indices,
        const float* __restrict__ baseW,
        const float* __restrict__ loraA,
        const float* __restrict__ loraB,
        float*       __restrict__ out,
        int n_rows)
{
    const int tid = threadIdx.x;
    const int d0  = tid * 4;

    ulonglong2 a2[R_];
    #pragma unroll
    for (int r = 0; r < R_; ++r) a2[r] = ldg128(loraA + r * D_ + d0);

    const int G = gridDim.x;
    int g = blockIdx.x;

    int idx_c = (g < n_rows) ? __ldg(indices + g) : -1;
    int idx_n = (g + G < n_rows) ? __ldg(indices + g + G) : -1;
    ulonglong2 x_c = (idx_c >= 0) ? ldg128(baseW + (size_t)idx_c * D_ + d0)
                                  : make_ulonglong2(0ull, 0ull);

    for (; g < n_rows; g += G) {
        int idx_nn = (g + 2 * G < n_rows) ? __ldg(indices + g + 2 * G) : -1;
        ulonglong2 x_n = (idx_n >= 0) ? ldg128(baseW + (size_t)idx_n * D_ + d0)
                                      : make_ulonglong2(0ull, 0ull);
        float2 cf = __ldg(&g_coef[g]);
        float4 b[4];
        loadB(loraB, idx_c, b);

        ull d01, d23;
        delta4(b, a2, d01, d23);

        ull cxd = dup_(cf.x), cyd = dup_(cf.y);
        ull o01 = ffma2(cxd, x_c.x, fmul2(cyd, d01));
        ull o23 = ffma2(cxd, x_c.y, fmul2(cyd, d23));
        stcs128(out + (size_t)g * D_ + d0, o01, o23);

        idx_c = idx_n; idx_n = idx_nn; x_c = x_n;
    }
}

extern "C" void kernel_launch(void* const* d_in, const int* in_sizes, int n_in,
                              void* d_out, int out_size)
{
    const int*   indices = (const int*)  d_in[0];
    const float* baseW   = (const float*)d_in[1];
    const float* loraA   = (const float*)d_in[2];
    const float* loraB   = (const float*)d_in[3];
    float*       out     = (float*)d_out;

    int n_rows = in_sizes[0];                 // 32768
    int gridAC = 2 * 148;                     // 2 CTAs/SM, persistent grid-stride
    if (gridAC > n_rows) gridAC = n_rows;
    int gridB  = (n_rows + 255) / 256;

    kA<<<gridAC, TPB>>>(indices, baseW, loraA, loraB, n_rows);
    kB<<<gridB, 256>>>(n_rows);
    kC<<<gridAC, TPB>>>(indices, baseW, loraA, loraB, out, n_rows);
}

// round 11
// speedup vs baseline: 1.3047x; 1.3045x over previous
#include <cuda_runtime.h>
#include <cstdint>

typedef unsigned long long ull;

#define TPB   256
#define R_    16
#define D_    1024
#define NWARP 8            // warps per block = column chunks per row
#define MAXROWS 65536

// ---- packed f32x2 helpers ----
__device__ __forceinline__ ull ffma2(ull a, ull b, ull c) {
    ull d;
    asm("fma.rn.f32x2 %0, %1, %2, %3;" : "=l"(d) : "l"(a), "l"(b), "l"(c));
    return d;
}
__device__ __forceinline__ ull fmul2(ull a, ull b) {
    ull d;
    asm("mul.rn.f32x2 %0, %1, %2;" : "=l"(d) : "l"(a), "l"(b));
    return d;
}
__device__ __forceinline__ float lo_(ull v) { return __int_as_float((int)(unsigned)(v & 0xffffffffull)); }
__device__ __forceinline__ float hi_(ull v) { return __int_as_float((int)(unsigned)(v >> 32)); }
__device__ __forceinline__ ull   dup_(float v) {
    ull d;
    asm("mov.b64 %0, {%1, %1};" : "=l"(d) : "r"(__float_as_uint(v)));
    return d;
}
__device__ __forceinline__ ulonglong2 ldg128(const void* p) {
    ulonglong2 v;
    asm("ld.global.nc.v2.u64 {%0, %1}, [%2];" : "=l"(v.x), "=l"(v.y) : "l"(p));
    return v;
}
__device__ __forceinline__ void stcs128(void* p, ull a, ull b) {
    asm volatile("st.global.cs.v2.u64 [%0], {%1, %2};" :: "l"(p), "l"(a), "l"(b));
}

// scratch (static device memory — allowed)
__device__ float4 g_part[MAXROWS * NWARP];   // per (row, warp-chunk): x2, y2, xy
__device__ float2 g_coef[MAXROWS];           // per row: cx, cy

// ---- helper: rank-16 delta for this thread's 4 columns ----
__device__ __forceinline__ void delta4(const float4 b[4], const ulonglong2 a2[R_],
                                       ull& d01, ull& d23)
{
    ull e01, e23;
    {
        ull bb = dup_(b[0].x);
        d01 = fmul2(bb, a2[0].x); d23 = fmul2(bb, a2[0].y);
        bb = dup_(b[0].y);
        e01 = fmul2(bb, a2[1].x); e23 = fmul2(bb, a2[1].y);
        bb = dup_(b[0].z);
        d01 = ffma2(bb, a2[2].x, d01); d23 = ffma2(bb, a2[2].y, d23);
        bb = dup_(b[0].w);
        e01 = ffma2(bb, a2[3].x, e01); e23 = ffma2(bb, a2[3].y, e23);
    }
    #pragma unroll
    for (int q = 1; q < 4; ++q) {
        ull bb = dup_(b[q].x);
        d01 = ffma2(bb, a2[4 * q + 0].x, d01); d23 = ffma2(bb, a2[4 * q + 0].y, d23);
        bb = dup_(b[q].y);
        e01 = ffma2(bb, a2[4 * q + 1].x, e01); e23 = ffma2(bb, a2[4 * q + 1].y, e23);
        bb = dup_(b[q].z);
        d01 = ffma2(bb, a2[4 * q + 2].x, d01); d23 = ffma2(bb, a2[4 * q + 2].y, d23);
        bb = dup_(b[q].w);
        e01 = ffma2(bb, a2[4 * q + 3].x, e01); e23 = ffma2(bb, a2[4 * q + 3].y, e23);
    }
    ull s01, s23;
    asm("add.rn.f32x2 %0, %1, %2;" : "=l"(s01) : "l"(d01), "l"(e01));
    asm("add.rn.f32x2 %0, %1, %2;" : "=l"(s23) : "l"(d23), "l"(e23));
    d01 = s01; d23 = s23;
}

__device__ __forceinline__ void loadB(const float* __restrict__ loraB, int idx, float4 b[4])
{
    if (idx >= 0) {
        const float4* p = reinterpret_cast<const float4*>(loraB + (size_t)idx * R_);
        b[0] = __ldg(p); b[1] = __ldg(p + 1); b[2] = __ldg(p + 2); b[3] = __ldg(p + 3);
    } else {
        b[0] = b[1] = b[2] = b[3] = make_float4(0.f, 0.f, 0.f, 0.f);
    }
}

// ================= Kernel A: partial sums (barrier-free) =================
__global__ __launch_bounds__(TPB, 2)
void kA(const int*   __restrict__ indices,
        const float* __restrict__ baseW,
        const float* __restrict__ loraA,
        const float* __restrict__ loraB,
        int n_rows)
{
    const int tid  = threadIdx.x;
    const int wid  = tid >> 5;
    const int lane = tid & 31;
    const int d0   = tid * 4;

    ulonglong2 a2[R_];
    #pragma unroll
    for (int r = 0; r < R_; ++r) a2[r] = ldg128(loraA + r * D_ + d0);

    const int G = gridDim.x;
    int g = blockIdx.x;

    int idx_c = (g < n_rows) ? __ldg(indices + g) : -1;
    int idx_n = (g + G < n_rows) ? __ldg(indices + g + G) : -1;
    ulonglong2 x_c = (idx_c >= 0) ? ldg128(baseW + (size_t)idx_c * D_ + d0)
                                  : make_ulonglong2(0ull, 0ull);

    for (; g < n_rows; g += G) {
        // pipeline: idx depth-2, x depth-1
        int idx_nn = (g + 2 * G < n_rows) ? __ldg(indices + g + 2 * G) : -1;
        ulonglong2 x_n = (idx_n >= 0) ? ldg128(baseW + (size_t)idx_n * D_ + d0)
                                      : make_ulonglong2(0ull, 0ull);
        float4 b[4];
        loadB(loraB, idx_c, b);

        ull d01, d23;
        delta4(b, a2, d01, d23);

        float x0 = lo_(x_c.x), x1 = hi_(x_c.x), x2c = lo_(x_c.y), x3 = hi_(x_c.y);
        float y0 = lo_(d01),   y1 = hi_(d01),   y2c = lo_(d23),   y3 = hi_(d23);

        // raw delta is 0.1 * (b @ A) — fold SCALING into partials via y*0.1 later?
        // No: keep delta unscaled here; scaling folded in kernel B/C consistently.
        float sx2 = fmaf(x0, x0, fmaf(x1, x1, fmaf(x2c, x2c, x3 * x3)));
        float sy2 = fmaf(y0, y0, fmaf(y1, y1, fmaf(y2c, y2c, y3 * y3)));
        float sxy = fmaf(x0, y0, fmaf(x1, y1, fmaf(x2c, y2c, x3 * y3)));

        #pragma unroll
        for (int off = 16; off > 0; off >>= 1) {
            sx2 += __shfl_xor_sync(0xffffffffu, sx2, off);
            sy2 += __shfl_xor_sync(0xffffffffu, sy2, off);
            sxy += __shfl_xor_sync(0xffffffffu, sxy, off);
        }
        if (lane == 0)
            g_part[(g << 3) | wid] = make_float4(sx2, sy2, sxy, 0.f);

        idx_c = idx_n; idx_n = idx_nn; x_c = x_n;
    }
}

// ================= Kernel B: reduce chunks + epilogue =================
__global__ __launch_bounds__(256)
void kB(int n_rows)
{
    int i = blockIdx.x * blockDim.x + threadIdx.x;
    if (i >= n_rows) return;

    float x2 = 0.f, y2r = 0.f, xyr = 0.f;
    #pragma unroll
    for (int w = 0; w < NWARP; ++w) {
        float4 p = g_part[(i << 3) | w];
        x2 += p.x; y2r += p.y; xyr += p.z;
    }
    // delta = SCALING * (b@A): partials were computed on raw b@A
    const float SC = 0.1f;
    float y2 = y2r * (SC * SC);
    float xy = xyr * SC;

    const float MAXN = 1.0f - 1e-5f;
    const float EPSN = 1e-5f;

    float nx = sqrtf(x2);
    float sx = (nx > MAXN) ? __fdividef(MAXN, fmaxf(nx, EPSN)) : 1.0f;
    float ny = sqrtf(y2);
    float sy = (ny > MAXN) ? __fdividef(MAXN, fmaxf(ny, EPSN)) : 1.0f;

    float X2 = sx * sx * x2;
    float Y2 = sy * sy * y2;
    float XY = sx * sy * xy;

    float A_  = 1.0f + 2.0f * XY + Y2;
    float B_  = 1.0f - X2;
    float den = fmaxf(1.0f + 2.0f * XY + X2 * Y2, 1e-15f);

    float n2 = (A_ * A_ * X2 + 2.0f * A_ * B_ * XY + B_ * B_ * Y2) / (den * den);
    float no = sqrtf(fmaxf(n2, 0.0f));
    float sf = (no > MAXN) ? __fdividef(MAXN, fmaxf(no, EPSN)) : 1.0f;

    float cx = __fdividef(sf * A_ * sx, den);
    float cy = __fdividef(sf * B_ * sy, den) * SC;   // fold SCALING into cy
    g_coef[i] = make_float2(cx, cy);
}

// ================= Kernel C: apply (barrier-free) =================
__global__ __launch_bounds__(TPB, 2)
void kC(const int*   __restrict__ indices,
        const float* __restrict__ baseW,
        const float* __restrict__ loraA,
        const float* __restrict__ loraB,
        float*       __restrict__ out,
        int n_rows)
{
    const int tid = threadIdx.x;
    const int d0  = tid * 4;

    ulonglong2 a2[R_];
    #pragma unroll
    for (int r = 0; r < R_; ++r) a2[r] = ldg128(loraA + r * D_ + d0);

    const int G = gridDim.x;
    int g = blockIdx.x;

    int idx_c = (g < n_rows) ? __ldg(indices + g) : -1;
    int idx_n = (g + G < n_rows) ? __ldg(indices + g + G) : -1;
    ulonglong2 x_c = (idx_c >= 0) ? ldg128(baseW + (size_t)idx_c * D_ + d0)
                                  : make_ulonglong2(0ull, 0ull);

    for (; g < n_rows; g += G) {
        int idx_nn = (g + 2 * G < n_rows) ? __ldg(indices + g + 2 * G) : -1;
        ulonglong2 x_n = (idx_n >= 0) ? ldg128(baseW + (size_t)idx_n * D_ + d0)
                                      : make_ulonglong2(0ull, 0ull);
        float2 cf = __ldg(&g_coef[g]);
        float4 b[4];
        loadB(loraB, idx_c, b);

        ull d01, d23;
        delta4(b, a2, d01, d23);

        ull cxd = dup_(cf.x), cyd = dup_(cf.y);
        ull o01 = ffma2(cxd, x_c.x, fmul2(cyd, d01));
        ull o23 = ffma2(cxd, x_c.y, fmul2(cyd, d23));
        stcs128(out + (size_t)g * D_ + d0, o01, o23);

        idx_c = idx_n; idx_n = idx_nn; x_c = x_n;
    }
}

extern "C" void kernel_launch(void* const* d_in, const int* in_sizes, int n_in,
                              void* d_out, int out_size)
{
    const int*   indices = (const int*)  d_in[0];
    const float* baseW   = (const float*)d_in[1];
    const float* loraA   = (const float*)d_in[2];
    const float* loraB   = (const float*)d_in[3];
    float*       out     = (float*)d_out;

    int n_rows = in_sizes[0];                 // 32768
    int gridAC = 2 * 148;                     // 2 CTAs/SM, persistent grid-stride
    if (gridAC > n_rows) gridAC = n_rows;
    int gridB  = (n_rows + 255) / 256;

    kA<<<gridAC, TPB>>>(indices, baseW, loraA, loraB, n_rows);
    kB<<<gridB, 256>>>(n_rows);
    kC<<<gridAC, TPB>>>(indices, baseW, loraA, loraB, out, n_rows);
}

// round 12
// speedup vs baseline: 1.3052x; 1.0004x over previous
#include <cuda_runtime.h>
#include <cstdint>

typedef unsigned long long ull;

#define TPB   256
#define R_    16
#define D_    1024
#define NWARP 8            // warps per block = column chunks per row
#define MAXROWS 65536

// ---- packed f32x2 helpers ----
__device__ __forceinline__ ull ffma2(ull a, ull b, ull c) {
    ull d;
    asm("fma.rn.f32x2 %0, %1, %2, %3;" : "=l"(d) : "l"(a), "l"(b), "l"(c));
    return d;
}
__device__ __forceinline__ ull fmul2(ull a, ull b) {
    ull d;
    asm("mul.rn.f32x2 %0, %1, %2;" : "=l"(d) : "l"(a), "l"(b));
    return d;
}
__device__ __forceinline__ float lo_(ull v) { return __int_as_float((int)(unsigned)(v & 0xffffffffull)); }
__device__ __forceinline__ float hi_(ull v) { return __int_as_float((int)(unsigned)(v >> 32)); }
__device__ __forceinline__ ull   dup_(float v) {
    ull d;
    asm("mov.b64 %0, {%1, %1};" : "=l"(d) : "r"(__float_as_uint(v)));
    return d;
}
__device__ __forceinline__ ulonglong2 ldg128(const void* p) {
    ulonglong2 v;
    asm("ld.global.nc.v2.u64 {%0, %1}, [%2];" : "=l"(v.x), "=l"(v.y) : "l"(p));
    return v;
}
__device__ __forceinline__ void stcs128(void* p, ull a, ull b) {
    asm volatile("st.global.cs.v2.u64 [%0], {%1, %2};" :: "l"(p), "l"(a), "l"(b));
}

// scratch (static device memory — allowed)
__device__ float4 g_part[MAXROWS * NWARP];   // per (row, warp-chunk): x2, y2, xy
__device__ float2 g_coef[MAXROWS];           // per row: cx, cy

// ---- helper: rank-16 delta for this thread's 4 columns ----
__device__ __forceinline__ void delta4(const float4 b[4], const ulonglong2 a2[R_],
                                       ull& d01, ull& d23)
{
    ull e01, e23;
    {
        ull bb = dup_(b[0].x);
        d01 = fmul2(bb, a2[0].x); d23 = fmul2(bb, a2[0].y);
        bb = dup_(b[0].y);
        e01 = fmul2(bb, a2[1].x); e23 = fmul2(bb, a2[1].y);
        bb = dup_(b[0].z);
        d01 = ffma2(bb, a2[2].x, d01); d23 = ffma2(bb, a2[2].y, d23);
        bb = dup_(b[0].w);
        e01 = ffma2(bb, a2[3].x, e01); e23 = ffma2(bb, a2[3].y, e23);
    }
    #pragma unroll
    for (int q = 1; q < 4; ++q) {
        ull bb = dup_(b[q].x);
        d01 = ffma2(bb, a2[4 * q + 0].x, d01); d23 = ffma2(bb, a2[4 * q + 0].y, d23);
        bb = dup_(b[q].y);
        e01 = ffma2(bb, a2[4 * q + 1].x, e01); e23 = ffma2(bb, a2[4 * q + 1].y, e23);
        bb = dup_(b[q].z);
        d01 = ffma2(bb, a2[4 * q + 2].x, d01); d23 = ffma2(bb, a2[4 * q + 2].y, d23);
        bb = dup_(b[q].w);
        e01 = ffma2(bb, a2[4 * q + 3].x, e01); e23 = ffma2(bb, a2[4 * q + 3].y, e23);
    }
    ull s01, s23;
    asm("add.rn.f32x2 %0, %1, %2;" : "=l"(s01) : "l"(d01), "l"(e01));
    asm("add.rn.f32x2 %0, %1, %2;" : "=l"(s23) : "l"(d23), "l"(e23));
    d01 = s01; d23 = s23;
}

__device__ __forceinline__ void loadB(const float* __restrict__ loraB, int idx, float4 b[4])
{
    if (idx >= 0) {
        const float4* p = reinterpret_cast<const float4*>(loraB + (size_t)idx * R_);
        b[0] = __ldg(p); b[1] = __ldg(p + 1); b[2] = __ldg(p + 2); b[3] = __ldg(p + 3);
    } else {
        b[0] = b[1] = b[2] = b[3] = make_float4(0.f, 0.f, 0.f, 0.f);
    }
}

// ================= Kernel A: partial sums (barrier-free) =================
__global__ __launch_bounds__(TPB, 2)
void kA(const int*   __restrict__ indices,
        const float* __restrict__ baseW,
        const float* __restrict__ loraA,
        const float* __restrict__ loraB,
        int n_rows)
{
    const int tid  = threadIdx.x;
    const int wid  = tid >> 5;
    const int lane = tid & 31;
    const int d0   = tid * 4;

    ulonglong2 a2[R_];
    #pragma unroll
    for (int r = 0; r < R_; ++r) a2[r] = ldg128(loraA + r * D_ + d0);

    const int G = gridDim.x;
    int g = blockIdx.x;

    int idx_c = (g < n_rows) ? __ldg(indices + g) : -1;
    int idx_n = (g + G < n_rows) ? __ldg(indices + g + G) : -1;
    ulonglong2 x_c = (idx_c >= 0) ? ldg128(baseW + (size_t)idx_c * D_ + d0)
                                  : make_ulonglong2(0ull, 0ull);

    for (; g < n_rows; g += G) {
        // pipeline: idx depth-2, x depth-1
        int idx_nn = (g + 2 * G < n_rows) ? __ldg(indices + g + 2 * G) : -1;
        ulonglong2 x_n = (idx_n >= 0) ? ldg128(baseW + (size_t)idx_n * D_ + d0)
                                      : make_ulonglong2(0ull, 0ull);
        float4 b[4];
        loadB(loraB, idx_c, b);

        ull d01, d23;
        delta4(b, a2, d01, d23);

        float x0 = lo_(x_c.x), x1 = hi_(x_c.x), x2c = lo_(x_c.y), x3 = hi_(x_c.y);
        float y0 = lo_(d01),   y1 = hi_(d01),   y2c = lo_(d23),   y3 = hi_(d23);

        // raw delta is 0.1 * (b @ A) — fold SCALING into partials via y*0.1 later?
        // No: keep delta unscaled here; scaling folded in kernel B/C consistently.
        float sx2 = fmaf(x0, x0, fmaf(x1, x1, fmaf(x2c, x2c, x3 * x3)));
        float sy2 = fmaf(y0, y0, fmaf(y1, y1, fmaf(y2c, y2c, y3 * y3)));
        float sxy = fmaf(x0, y0, fmaf(x1, y1, fmaf(x2c, y2c, x3 * y3)));

        #pragma unroll
        for (int off = 16; off > 0; off >>= 1) {
            sx2 += __shfl_xor_sync(0xffffffffu, sx2, off);
            sy2 += __shfl_xor_sync(0xffffffffu, sy2, off);
            sxy += __shfl_xor_sync(0xffffffffu, sxy, off);
        }
        if (lane == 0)
            g_part[(g << 3) | wid] = make_float4(sx2, sy2, sxy, 0.f);

        idx_c = idx_n; idx_n = idx_nn; x_c = x_n;
    }
}

// ================= Kernel B: reduce chunks + epilogue =================
__global__ __launch_bounds__(256)
void kB(int n_rows)
{
    int i = blockIdx.x * blockDim.x + threadIdx.x;
    if (i >= n_rows) return;

    float x2 = 0.f, y2r = 0.f, xyr = 0.f;
    #pragma unroll
    for (int w = 0; w < NWARP; ++w) {
        float4 p = g_part[(i << 3) | w];
        x2 += p.x; y2r += p.y; xyr += p.z;
    }
    // delta = SCALING * (b@A): partials were computed on raw b@A
    const float SC = 0.1f;
    float y2 = y2r * (SC * SC);
    float xy = xyr * SC;

    const float MAXN = 1.0f - 1e-5f;
    const float EPSN = 1e-5f;

    float nx = sqrtf(x2);
    float sx = (nx > MAXN) ? __fdividef(MAXN, fmaxf(nx, EPSN)) : 1.0f;
    float ny = sqrtf(y2);
    float sy = (ny > MAXN) ? __fdividef(MAXN, fmaxf(ny, EPSN)) : 1.0f;

    float X2 = sx * sx * x2;
    float Y2 = sy * sy * y2;
    float XY = sx * sy * xy;

    float A_  = 1.0f + 2.0f * XY + Y2;
    float B_  = 1.0f - X2;
    float den = fmaxf(1.0f + 2.0f * XY + X2 * Y2, 1e-15f);

    float n2 = (A_ * A_ * X2 + 2.0f * A_ * B_ * XY + B_ * B_ * Y2) / (den * den);
    float no = sqrtf(fmaxf(n2, 0.0f));
    float sf = (no > MAXN) ? __fdividef(MAXN, fmaxf(no, EPSN)) : 1.0f;

    float cx = __fdividef(sf * A_ * sx, den);
    float cy = __fdividef(sf * B_ * sy, den) * SC;   // fold SCALING into cy
    g_coef[i] = make_float2(cx, cy);
}

// ================= Kernel C: apply (barrier-free) =================
__global__ __launch_bounds__(TPB, 2)
void kC(const int*   __restrict__ indices,
        const float* __restrict__ baseW,
        const float* __restrict__ loraA,
        const float* __restrict__ loraB,
        float*       __restrict__ out,
        int n_rows)
{
    const int tid = threadIdx.x;
    const int d0  = tid * 4;

    ulonglong2 a2[R_];
    #pragma unroll
    for (int r = 0; r < R_; ++r) a2[r] = ldg128(loraA + r * D_ + d0);

    const int G = gridDim.x;
    int g = blockIdx.x;

    int idx_c = (g < n_rows) ? __ldg(indices + g) : -1;
    int idx_n = (g + G < n_rows) ? __ldg(indices + g + G) : -1;
    ulonglong2 x_c = (idx_c >= 0) ? ldg128(baseW + (size_t)idx_c * D_ + d0)
                                  : make_ulonglong2(0ull, 0ull);

    for (; g < n_rows; g += G) {
        int idx_nn = (g + 2 * G < n_rows) ? __ldg(indices + g + 2 * G) : -1;
        ulonglong2 x_n = (idx_n >= 0) ? ldg128(baseW + (size_t)idx_n * D_ + d0)
                                      : make_ulonglong2(0ull, 0ull);
        float2 cf = __ldg(&g_coef[g]);
        float4 b[4];
        loadB(loraB, idx_c, b);

        ull d01, d23;
        delta4(b, a2, d01, d23);

        ull cxd = dup_(cf.x), cyd = dup_(cf.y);
        ull o01 = ffma2(cxd, x_c.x, fmul2(cyd, d01));
        ull o23 = ffma2(cxd, x_c.y, fmul2(cyd, d23));
        stcs128(out + (size_t)g * D_ + d0, o01, o23);

        idx_c = idx_n; idx_n = idx_nn; x_c = x_n;
    }
}

extern "C" void kernel_launch(void* const* d_in, const int* in_sizes, int n_in,
                              void* d_out, int out_size)
{
    const int*   indices = (const int*)  d_in[0];
    const float* baseW   = (const float*)d_in[1];
    const float* loraA   = (const float*)d_in[2];
    const float* loraB   = (const float*)d_in[3];
    float*       out     = (float*)d_out;

    int n_rows = in_sizes[0];                 // 32768
    int gridAC = 2 * 148;                     // 2 CTAs/SM, persistent grid-stride
    if (gridAC > n_rows) gridAC = n_rows;
    int gridB  = (n_rows + 255) / 256;

    kA<<<gridAC, TPB>>>(indices, baseW, loraA, loraB, n_rows);
    kB<<<gridB, 256>>>(n_rows);
    kC<<<gridAC, TPB>>>(indices, baseW, loraA, loraB, out, n_rows);
}

// round 13
// speedup vs baseline: 2.7415x; 2.1004x over previous
#include <cuda_runtime.h>
#include <cstdint>

typedef unsigned long long ull;

#define TPB   256
#define NB    8
#define R_    16
#define D_    1024

// ---- packed f32x2 helpers ----
__device__ __forceinline__ ull ffma2(ull a, ull b, ull c) {
    ull d;
    asm("fma.rn.f32x2 %0, %1, %2, %3;" : "=l"(d) : "l"(a), "l"(b), "l"(c));
    return d;
}
__device__ __forceinline__ ull fmul2(ull a, ull b) {
    ull d;
    asm("mul.rn.f32x2 %0, %1, %2;" : "=l"(d) : "l"(a), "l"(b));
    return d;
}
__device__ __forceinline__ ull fadd2(ull a, ull b) {
    ull d;
    asm("add.rn.f32x2 %0, %1, %2;" : "=l"(d) : "l"(a), "l"(b));
    return d;
}
__device__ __forceinline__ float lo_(ull v) { return __int_as_float((int)(unsigned)(v & 0xffffffffull)); }
__device__ __forceinline__ float hi_(ull v) { return __int_as_float((int)(unsigned)(v >> 32)); }
__device__ __forceinline__ ull   dup_(float v) {
    ull d;
    asm("mov.b64 %0, {%1, %1};" : "=l"(d) : "r"(__float_as_uint(v)));
    return d;
}
__device__ __forceinline__ ull pack2_(float l, float h) {
    ull d;
    asm("mov.b64 %0, {%1, %2};" : "=l"(d) : "r"(__float_as_uint(l)), "r"(__float_as_uint(h)));
    return d;
}
__device__ __forceinline__ ulonglong2 ldg128(const void* p) {
    ulonglong2 v;
    asm("ld.global.nc.v2.u64 {%0, %1}, [%2];" : "=l"(v.x), "=l"(v.y) : "l"(p));
    return v;
}
__device__ __forceinline__ void stcs128(void* p, ull a, ull b) {
    asm volatile("st.global.cs.v2.u64 [%0], {%1, %2};" :: "l"(p), "l"(a), "l"(b));
}
__device__ __forceinline__ unsigned sptr(const void* p) {
    return (unsigned)__cvta_generic_to_shared(p);
}
__device__ __forceinline__ void cpa16(unsigned dst, const void* src) {
    asm volatile("cp.async.cg.shared.global [%0], [%1], 16;" :: "r"(dst), "l"(src));
}

// ---- dynamic smem layout (per CTA, ~78 KB) ----
#define XS_OFF   0                       // ulonglong2 [2][NB][TPB]   65536 B
#define RED2_OFF 65536                   // ull   [NB][TPB/2]          8192 B
#define RED1_OFF 73728                   // float [NB][TPB/4]          2048 B
#define SB_OFF   75776                   // ull   [2][NB][R_]          2048 B
#define SIDX_OFF 77824                   // int   [2][NB]                64 B
#define SCX_OFF  77888                   // ull   [NB]                   64 B
#define SCY_OFF  77952                   // ull   [NB]                   64 B
#define SMEM_TOTAL 78016

__global__ __launch_bounds__(TPB, 2)
void rlora_kernel(const int*   __restrict__ indices,
                  const float* __restrict__ baseW,
                  const float* __restrict__ loraA,
                  const float* __restrict__ loraB,
                  float*       __restrict__ out,
                  int n_rows, int nbatch)
{
    extern __shared__ char smem_raw[];
    ulonglong2 (*xs)[NB][TPB]    = reinterpret_cast<ulonglong2(*)[NB][TPB]>(smem_raw + XS_OFF);
    ull   (*red2)[TPB / 2]       = reinterpret_cast<ull(*)[TPB / 2]>(smem_raw + RED2_OFF);
    float (*red1)[TPB / 4]       = reinterpret_cast<float(*)[TPB / 4]>(smem_raw + RED1_OFF);
    ull   (*sb)[NB][R_]          = reinterpret_cast<ull(*)[NB][R_]>(smem_raw + SB_OFF);
    int   (*sidx)[NB]            = reinterpret_cast<int(*)[NB]>(smem_raw + SIDX_OFF);
    ull*  scx                    = reinterpret_cast<ull*>(smem_raw + SCX_OFF);
    ull*  scy                    = reinterpret_cast<ull*>(smem_raw + SCY_OFF);

    const int tid  = threadIdx.x;
    const int wid  = tid >> 5;
    const int lane = tid & 31;
    const int d0   = tid * 4;            // this lane owns columns d0..d0+3

    // lora_A register-resident: a2[r] = A[r][d0..d0+3]  (64 regs)
    ulonglong2 a2[R_];
    #pragma unroll
    for (int r = 0; r < R_; ++r) a2[r] = ldg128(loraA + r * D_ + d0);

    const int S    = gridDim.x;
    const int b0   = blockIdx.x;
    const int kmax = (nbatch - b0 + S - 1) / S;

    // ---------------- prologue ----------------
    // issue cp.async group for batch 0 (indices read directly)
    #pragma unroll
    for (int row = 0; row < NB; ++row) {
        int g = b0 * NB + row;
        if (g < n_rows) {
            int idx = __ldg(indices + g);
            cpa16(sptr(&xs[0][row][tid]), baseW + (size_t)idx * D_ + d0);
        }
    }
    asm volatile("cp.async.commit_group;");
    // stage sidx slot 1 = batch 1 indices; sb slot 0 = batch 0 b-rows
    if (tid < NB) {
        int g = (b0 + S) * NB + tid;
        sidx[1][tid] = ((b0 + S) < nbatch && g < n_rows) ? __ldg(indices + g) : -1;
    }
    if (tid < NB * R_) {
        int row = tid >> 4, r = tid & 15;
        int g = b0 * NB + row;
        sb[0][row][r] = (g < n_rows)
            ? dup_(0.1f * __ldg(loraB + (size_t)__ldg(indices + g) * R_ + r)) : 0ull;
    }
    __syncthreads();

    for (int k = 0; k < kmax; ++k) {
        const int  buf      = k & 1;
        const bool havenext = (k + 1) < kmax;

        // ---- step 1: cp.async batch k+1 into xs[buf^1] ----
        #pragma unroll
        for (int row = 0; row < NB; ++row) {
            int idx = havenext ? sidx[(k + 1) & 1][row] : -1;
            if (idx >= 0)
                cpa16(sptr(&xs[buf ^ 1][row][tid]), baseW + (size_t)idx * D_ + d0);
        }
        asm volatile("cp.async.commit_group;");

        // ---- step 2: stage sidx(batch k+2) -> slot k&1 ----
        if (tid < NB) {
            long long g = (long long)(b0 + (k + 2) * S) * NB + tid;
            sidx[buf][tid] = ((k + 2) < kmax && g < n_rows) ? __ldg(indices + g) : -1;
        }
        // ---- step 3: stage sb(batch k+1) -> sb[buf^1] ----
        if (tid < NB * R_) {
            int row = tid >> 4, r = tid & 15;
            int idx = havenext ? sidx[(k + 1) & 1][row] : -1;
            sb[buf ^ 1][row][r] = (idx >= 0)
                ? dup_(0.1f * __ldg(loraB + (size_t)idx * R_ + r)) : 0ull;
        }

        // ---- step 4: batch k copies complete (own slices only) ----
        asm volatile("cp.async.wait_group 1;" ::: "memory");

        // ---- step 5: compute delta + prefolded partials ----
        ulonglong2 xk[NB], dvk[NB];
        #pragma unroll
        for (int row = 0; row < NB; ++row) {
            ulonglong2 xv = xs[buf][row][tid];     // this thread's own copy
            xk[row] = xv;

            const ulonglong2* bp = reinterpret_cast<const ulonglong2*>(sb[buf][row]);
            ulonglong2 b01 = bp[0];
            ull ax0 = fmul2(b01.x, a2[0].x), ay0 = fmul2(b01.x, a2[0].y);
            ull ax1 = fmul2(b01.y, a2[1].x), ay1 = fmul2(b01.y, a2[1].y);
            #pragma unroll
            for (int kk = 1; kk < R_ / 2; ++kk) {
                ulonglong2 b = bp[kk];
                ax0 = ffma2(b.x, a2[2 * kk].x,     ax0);
                ay0 = ffma2(b.x, a2[2 * kk].y,     ay0);
                ax1 = ffma2(b.y, a2[2 * kk + 1].x, ax1);
                ay1 = ffma2(b.y, a2[2 * kk + 1].y, ay1);
            }
            dvk[row].x = fadd2(ax0, ax1);
            dvk[row].y = fadd2(ay0, ay1);

            float x0 = lo_(xv.x), x1 = hi_(xv.x), x2c = lo_(xv.y), x3 = hi_(xv.y);
            float y0 = lo_(dvk[row].x), y1 = hi_(dvk[row].x);
            float y2c = lo_(dvk[row].y), y3 = hi_(dvk[row].y);

            float x2p = fmaf(x0, x0, fmaf(x1, x1, fmaf(x2c, x2c, x3 * x3)));
            float xyp = fmaf(x0, y0, fmaf(x1, y1, fmaf(x2c, y2c, x3 * y3)));
            float y2p = fmaf(y0, y0, fmaf(y1, y1, fmaf(y2c, y2c, y3 * y3)));

            x2p += __shfl_xor_sync(0xffffffffu, x2p, 16);
            xyp += __shfl_xor_sync(0xffffffffu, xyp, 16);
            y2p += __shfl_xor_sync(0xffffffffu, y2p, 16);
            y2p += __shfl_xor_sync(0xffffffffu, y2p, 8);
            if (lane < 16) red2[row][wid * 16 + lane] = pack2_(x2p, xyp);
            if (lane < 8)  red1[row][wid * 8 + lane]  = y2p;
        }
        __syncthreads();

        // ---- step 6: warp w reduces row w + epilogue (all 8 warps busy) ----
        {
            const ulonglong2* p2 = reinterpret_cast<const ulonglong2*>(red2[wid]);
            ulonglong2 v0 = p2[lane], v1 = p2[lane + 32];
            ull sp = fadd2(fadd2(v0.x, v0.y), fadd2(v1.x, v1.y));
            const float* r1 = red1[wid];
            float s2 = r1[lane] + r1[lane + 32];

            float a0 = lo_(sp), a1 = hi_(sp);
            #pragma unroll
            for (int off = 16; off > 0; off >>= 1) {
                a0 += __shfl_xor_sync(0xffffffffu, a0, off);
                a1 += __shfl_xor_sync(0xffffffffu, a1, off);
                s2 += __shfl_xor_sync(0xffffffffu, s2, off);
            }
            if (lane == 0) {
                const float MAXN = 1.0f - 1e-5f;
                const float EPSN = 1e-5f;
                float x2 = a0, xy = a1, y2 = s2;

                float nx = sqrtf(x2);
                float sx = (nx > MAXN) ? __fdividef(MAXN, fmaxf(nx, EPSN)) : 1.0f;
                float ny = sqrtf(y2);
                float sy = (ny > MAXN) ? __fdividef(MAXN, fmaxf(ny, EPSN)) : 1.0f;

                float X2 = sx * sx * x2;
                float Y2 = sy * sy * y2;
                float XY = sx * sy * xy;

                float A_  = 1.0f + 2.0f * XY + Y2;
                float B_  = 1.0f - X2;
                float den = fmaxf(1.0f + 2.0f * XY + X2 * Y2, 1e-15f);

                float n2 = (A_ * A_ * X2 + 2.0f * A_ * B_ * XY + B_ * B_ * Y2)
                           / (den * den);
                float no = sqrtf(fmaxf(n2, 0.0f));
                float sf = (no > MAXN) ? __fdividef(MAXN, fmaxf(no, EPSN)) : 1.0f;

                scx[wid] = dup_(__fdividef(sf * A_ * sx, den));
                scy[wid] = dup_(__fdividef(sf * B_ * sy, den));
            }
        }
        __syncthreads();

        // ---- step 7: store batch k (x/delta from registers) ----
        const long long row0 = (long long)(b0 + k * S) * NB;
        #pragma unroll
        for (int row = 0; row < NB; ++row) {
            long long g = row0 + row;
            if (g < n_rows) {
                ull o0 = ffma2(scx[row], xk[row].x, fmul2(scy[row], dvk[row].x));
                ull o1 = ffma2(scx[row], xk[row].y, fmul2(scy[row], dvk[row].y));
                stcs128(out + (size_t)g * D_ + d0, o0, o1);
            }
        }
    }
}

extern "C" void kernel_launch(void* const* d_in, const int* in_sizes, int n_in,
                              void* d_out, int out_size)
{
    const int*   indices = (const int*)  d_in[0];
    const float* baseW   = (const float*)d_in[1];
    const float* loraA   = (const float*)d_in[2];
    const float* loraB   = (const float*)d_in[3];
    float*       out     = (float*)d_out;

    int n_rows = in_sizes[0];                    // 32768
    int nbatch = (n_rows + NB - 1) / NB;         // 4096
    int grid   = nbatch < 2 * 148 ? nbatch : 2 * 148;   // 2 CTAs/SM (smem-capped)

    cudaFuncSetAttribute(rlora_kernel,
                         cudaFuncAttributeMaxDynamicSharedMemorySize, SMEM_TOTAL);
    rlora_kernel<<<grid, TPB, SMEM_TOTAL>>>(indices, baseW, loraA, loraB, out,
                                            n_rows, nbatch);
}